// round 8
// baseline (speedup 1.0000x reference)
#include <cuda_runtime.h>

// LocalConvolutionMix: per-pixel local conv, 3x3(pad1) + 5x5(pad2) branches.
// x:  [4, 256, 56, 56] f32
// w1: [4, 1, 32, 9,  56, 56]
// w2: [4, 1, 32, 25, 56, 56]
// out:[4, 2, 1, 256, 56, 56]
//
// Block (28,8)=224 thr, one block per (h-tile, v, n): weights hit DRAM once.
// 8 channel groups processed as two in-block passes of 4 (16 accs live) to
// fit 5 blocks/SM. w2 rows software-pipelined; w1 inline (L2 hits on pass 2).

#define N_    4
#define C_    256
#define H_    56
#define W_    56
#define WC_   32
#define GPB_  8
#define TH_   8
#define TW_   28
#define HW_   (H_*W_)
#define TCOL_ 64        // smem row: cols 4..59 = x[0..55], halo at 2,3,60,61

__global__ __launch_bounds__(TW_*TH_, 5)
void localconv_mix_kernel(const float* __restrict__ x,
                          const float* __restrict__ w1,
                          const float* __restrict__ w2,
                          float* __restrict__ out)
{
    __shared__ __align__(16) float xs[GPB_][TH_ + 4][TCOL_];

    const int tx = threadIdx.x;            // 0..27
    const int ty = threadIdx.y;            // 0..7
    const int h0 = blockIdx.x * TH_;
    const int v  = blockIdx.y;             // 0..31
    const int n  = blockIdx.z;

    const int tid = ty * TW_ + tx;         // 0..223

    // ---- stage x tile: aligned float4 interior, zeroed halo cols ----
    {
        const int f4   = tid % 14;         // float4 index in row (0..13)
        const int rowi = tid / 14;         // 0..15
        #pragma unroll
        for (int it = 0; it < 6; it++) {
            const int row = rowi + 16 * it;          // 0..95
            const int g = row / 12;
            const int r = row - g * 12;
            const int hh = h0 - 2 + r;
            float4 val = make_float4(0.f, 0.f, 0.f, 0.f);
            if (hh >= 0 && hh < H_) {
                const int c = g * WC_ + v;
                val = *(const float4*)(x + (((n * C_ + c) * H_ + hh) * W_ + 4 * f4));
            }
            *(float4*)&xs[g][r][4 + 4 * f4] = val;
        }
        if (tid < 96) {
            const int g = tid / 12;
            const int r = tid - g * 12;
            xs[g][r][2]  = 0.f; xs[g][r][3]  = 0.f;
            xs[g][r][60] = 0.f; xs[g][r][61] = 0.f;
        }
    }
    __syncthreads();

    const int h  = h0 + ty;
    const int w0 = 2 * tx;
    const int pix = h * W_ + w0;

    const float* w2p = w2 + (n * WC_ + v) * 25 * HW_ + pix;
    const float* w1p = w1 + (n * WC_ + v) * 9  * HW_ + pix;

    // two passes over channel groups; each pass keeps only 16 accumulators
    #pragma unroll 1
    for (int pass = 0; pass < 2; pass++) {
        const int gbase = pass * 4;

        float2 a1[4], a2[4];
        #pragma unroll
        for (int g = 0; g < 4; g++) {
            a1[g] = make_float2(0.f, 0.f);
            a2[g] = make_float2(0.f, 0.f);
        }

        // depth-1 pipeline on the heavy w2 stream
        float2 w2c[5];
        #pragma unroll
        for (int j = 0; j < 5; j++)
            w2c[j] = __ldg((const float2*)(w2p + j * HW_));   // ki=0 row

        #pragma unroll
        for (int ki = 0; ki < 5; ki++) {
            float2 w2n[5];
            if (ki < 4) {
                #pragma unroll
                for (int j = 0; j < 5; j++)
                    w2n[j] = __ldg((const float2*)(w2p + ((ki + 1) * 5 + j) * HW_));
            }

            const bool mid = (ki >= 1 && ki <= 3);
            float2 w1c[3];
            if (mid) {
                #pragma unroll
                for (int j = 0; j < 3; j++)
                    w1c[j] = __ldg((const float2*)(w1p + ((ki - 1) * 3 + j) * HW_));
            }

            #pragma unroll
            for (int g = 0; g < 4; g++) {
                // window x[w0-2 .. w0+3] at smem cols w0+2 .. w0+7
                const float* row = &xs[gbase + g][ty + ki][w0 + 2];
                const float2 p01 = *(const float2*)(row + 0);
                const float2 p23 = *(const float2*)(row + 2);
                const float2 p45 = *(const float2*)(row + 4);
                const float x0 = p01.x, x1 = p01.y, x2 = p23.x,
                            x3 = p23.y, x4 = p45.x, x5 = p45.y;

                a2[g].x = fmaf(w2c[0].x, x0, a2[g].x);
                a2[g].y = fmaf(w2c[0].y, x1, a2[g].y);
                a2[g].x = fmaf(w2c[1].x, x1, a2[g].x);
                a2[g].y = fmaf(w2c[1].y, x2, a2[g].y);
                a2[g].x = fmaf(w2c[2].x, x2, a2[g].x);
                a2[g].y = fmaf(w2c[2].y, x3, a2[g].y);
                a2[g].x = fmaf(w2c[3].x, x3, a2[g].x);
                a2[g].y = fmaf(w2c[3].y, x4, a2[g].y);
                a2[g].x = fmaf(w2c[4].x, x4, a2[g].x);
                a2[g].y = fmaf(w2c[4].y, x5, a2[g].y);

                if (mid) {
                    a1[g].x = fmaf(w1c[0].x, x1, a1[g].x);
                    a1[g].y = fmaf(w1c[0].y, x2, a1[g].y);
                    a1[g].x = fmaf(w1c[1].x, x2, a1[g].x);
                    a1[g].y = fmaf(w1c[1].y, x3, a1[g].y);
                    a1[g].x = fmaf(w1c[2].x, x3, a1[g].x);
                    a1[g].y = fmaf(w1c[2].y, x4, a1[g].y);
                }
            }

            #pragma unroll
            for (int j = 0; j < 5; j++) w2c[j] = w2n[j];
        }

        // streaming stores: output never re-read
        #pragma unroll
        for (int g = 0; g < 4; g++) {
            const int c = (gbase + g) * WC_ + v;
            __stcs((float2*)&out[((n * 2 + 0) * C_ + c) * HW_ + pix], a1[g]);
            __stcs((float2*)&out[((n * 2 + 1) * C_ + c) * HW_ + pix], a2[g]);
        }
    }
}

extern "C" void kernel_launch(void* const* d_in, const int* in_sizes, int n_in,
                              void* d_out, int out_size)
{
    const float* x  = (const float*)d_in[0];
    const float* w1 = (const float*)d_in[1];
    const float* w2 = (const float*)d_in[2];
    float* out = (float*)d_out;

    dim3 block(TW_, TH_);          // 224 threads
    dim3 grid(H_ / TH_, WC_, N_);  // (7, 32, 4) = 896 blocks
    localconv_mix_kernel<<<grid, block>>>(x, w1, w2, out);
}

// round 9
// speedup vs baseline: 2.4206x; 2.4206x over previous
#include <cuda_runtime.h>

// LocalConvolutionMix: per-pixel local conv, 3x3(pad1) + 5x5(pad2) branches.
// x:  [4, 256, 56, 56] f32
// w1: [4, 1, 32, 9,  56, 56]
// w2: [4, 1, 32, 25, 56, 56]
// out:[4, 2, 1, 256, 56, 56]
//
// Block (28,8)=224 thr; thread = 2 adjacent W px x ALL 8 channel groups x 2
// branches. One block per (h-tile, v, n): weights hit DRAM exactly once.
// Depth-1 register pipeline on weight rows + L2 prefetch 1-2 rows ahead,
// so pipelined LDGs see L2-hit latency instead of DRAM latency.

#define N_    4
#define C_    256
#define H_    56
#define W_    56
#define WC_   32
#define GPB_  8
#define TH_   8
#define TW_   28
#define HW_   (H_*W_)
#define TCOL_ 64        // smem row: cols 4..59 = x[0..55], halo at 2,3,60,61

#define PF_L2(p) asm volatile("prefetch.global.L2 [%0];" :: "l"(p))

__global__ __launch_bounds__(TW_*TH_, 4)
void localconv_mix_kernel(const float* __restrict__ x,
                          const float* __restrict__ w1,
                          const float* __restrict__ w2,
                          float* __restrict__ out)
{
    __shared__ __align__(16) float xs[GPB_][TH_ + 4][TCOL_];

    const int tx = threadIdx.x;            // 0..27
    const int ty = threadIdx.y;            // 0..7
    const int h0 = blockIdx.x * TH_;
    const int v  = blockIdx.y;             // 0..31
    const int n  = blockIdx.z;

    const int tid = ty * TW_ + tx;         // 0..223

    // ---- stage x tile: aligned float4 interior, zeroed halo cols ----
    {
        const int f4   = tid % 14;         // float4 index in row (0..13)
        const int rowi = tid / 14;         // 0..15
        #pragma unroll
        for (int it = 0; it < 6; it++) {
            const int row = rowi + 16 * it;          // 0..95
            const int g = row / 12;
            const int r = row - g * 12;
            const int hh = h0 - 2 + r;
            float4 val = make_float4(0.f, 0.f, 0.f, 0.f);
            if (hh >= 0 && hh < H_) {
                const int c = g * WC_ + v;
                val = *(const float4*)(x + (((n * C_ + c) * H_ + hh) * W_ + 4 * f4));
            }
            *(float4*)&xs[g][r][4 + 4 * f4] = val;
        }
        if (tid < 96) {
            const int g = tid / 12;
            const int r = tid - g * 12;
            xs[g][r][2]  = 0.f; xs[g][r][3]  = 0.f;
            xs[g][r][60] = 0.f; xs[g][r][61] = 0.f;
        }
    }

    const int h  = h0 + ty;
    const int w0 = 2 * tx;
    const int pix = h * W_ + w0;

    const float* w2p = w2 + (n * WC_ + v) * 25 * HW_ + pix;
    const float* w1p = w1 + (n * WC_ + v) * 9  * HW_ + pix;

    // L2 prefetch ahead of the register pipeline (issued before the sync so
    // they overlap the staging barrier too)
    #pragma unroll
    for (int j = 0; j < 5; j++) { PF_L2(w2p + (5 + j) * HW_); }
    #pragma unroll
    for (int j = 0; j < 5; j++) { PF_L2(w2p + (10 + j) * HW_); }
    #pragma unroll
    for (int j = 0; j < 3; j++) { PF_L2(w1p + j * HW_); }
    #pragma unroll
    for (int j = 0; j < 3; j++) { PF_L2(w1p + (3 + j) * HW_); }

    __syncthreads();

    float2 a1[GPB_], a2[GPB_];
    #pragma unroll
    for (int g = 0; g < GPB_; g++) {
        a1[g] = make_float2(0.f, 0.f);
        a2[g] = make_float2(0.f, 0.f);
    }

    // --- depth-1 register pipeline: row ki prefetched during ki-1 ---
    float2 w2c[5], w1c[3];
    #pragma unroll
    for (int j = 0; j < 5; j++)
        w2c[j] = __ldg((const float2*)(w2p + j * HW_));   // ki=0 row

    #pragma unroll
    for (int ki = 0; ki < 5; ki++) {
        float2 w2n[5], w1n[3];
        if (ki < 4) {
            #pragma unroll
            for (int j = 0; j < 5; j++)
                w2n[j] = __ldg((const float2*)(w2p + ((ki + 1) * 5 + j) * HW_));
            if (ki + 1 >= 1 && ki + 1 <= 3) {
                #pragma unroll
                for (int j = 0; j < 3; j++)
                    w1n[j] = __ldg((const float2*)(w1p + (ki * 3 + j) * HW_));
            }
        }
        // keep L2 1-2 rows ahead of the register pipeline
        if (ki < 2) {
            #pragma unroll
            for (int j = 0; j < 5; j++) { PF_L2(w2p + ((ki + 3) * 5 + j) * HW_); }
        }
        if (ki == 0) {
            #pragma unroll
            for (int j = 0; j < 3; j++) { PF_L2(w1p + (6 + j) * HW_); }
        }

        const bool mid = (ki >= 1 && ki <= 3);

        #pragma unroll
        for (int g = 0; g < GPB_; g++) {
            // window x[w0-2 .. w0+3] at smem cols w0+2 .. w0+7 (8B aligned)
            const float* row = &xs[g][ty + ki][w0 + 2];
            const float2 p01 = *(const float2*)(row + 0);
            const float2 p23 = *(const float2*)(row + 2);
            const float2 p45 = *(const float2*)(row + 4);
            const float x0 = p01.x, x1 = p01.y, x2 = p23.x,
                        x3 = p23.y, x4 = p45.x, x5 = p45.y;

            a2[g].x = fmaf(w2c[0].x, x0, a2[g].x);
            a2[g].y = fmaf(w2c[0].y, x1, a2[g].y);
            a2[g].x = fmaf(w2c[1].x, x1, a2[g].x);
            a2[g].y = fmaf(w2c[1].y, x2, a2[g].y);
            a2[g].x = fmaf(w2c[2].x, x2, a2[g].x);
            a2[g].y = fmaf(w2c[2].y, x3, a2[g].y);
            a2[g].x = fmaf(w2c[3].x, x3, a2[g].x);
            a2[g].y = fmaf(w2c[3].y, x4, a2[g].y);
            a2[g].x = fmaf(w2c[4].x, x4, a2[g].x);
            a2[g].y = fmaf(w2c[4].y, x5, a2[g].y);

            if (mid) {
                a1[g].x = fmaf(w1c[0].x, x1, a1[g].x);
                a1[g].y = fmaf(w1c[0].y, x2, a1[g].y);
                a1[g].x = fmaf(w1c[1].x, x2, a1[g].x);
                a1[g].y = fmaf(w1c[1].y, x3, a1[g].y);
                a1[g].x = fmaf(w1c[2].x, x3, a1[g].x);
                a1[g].y = fmaf(w1c[2].y, x4, a1[g].y);
            }
        }

        #pragma unroll
        for (int j = 0; j < 5; j++) w2c[j] = w2n[j];
        #pragma unroll
        for (int j = 0; j < 3; j++) w1c[j] = w1n[j];
    }

    // streaming stores: output never re-read, keep L2 for weights
    #pragma unroll
    for (int g = 0; g < GPB_; g++) {
        const int c = g * WC_ + v;
        __stcs((float2*)&out[((n * 2 + 0) * C_ + c) * HW_ + pix], a1[g]);
        __stcs((float2*)&out[((n * 2 + 1) * C_ + c) * HW_ + pix], a2[g]);
    }
}

extern "C" void kernel_launch(void* const* d_in, const int* in_sizes, int n_in,
                              void* d_out, int out_size)
{
    const float* x  = (const float*)d_in[0];
    const float* w1 = (const float*)d_in[1];
    const float* w2 = (const float*)d_in[2];
    float* out = (float*)d_out;

    dim3 block(TW_, TH_);          // 224 threads
    dim3 grid(H_ / TH_, WC_, N_);  // (7, 32, 4) = 896 blocks
    localconv_mix_kernel<<<grid, block>>>(x, w1, w2, out);
}